// round 2
// baseline (speedup 1.0000x reference)
#include <cuda_runtime.h>
#include <cuda_fp16.h>
#include <cstdint>

// ============================================================================
// Problem constants
// ============================================================================
#define T_TOKENS 4096
#define IN_F     4096
#define OUT_F    4096
#define NNZ      512

// GEMM tiling
static constexpr int BM = 128;
static constexpr int BN = 128;
static constexpr int BK = 64;                 // fp16 -> 128B rows (SW128 atom)
static constexpr int KITERS = IN_F / BK;      // 64
static constexpr int STAGES = 3;
static constexpr int STAGE_BYTES = (BM * BK + BN * BK) * 2;  // 32768
static constexpr int SMEM_TOTAL = STAGES * STAGE_BYTES;      // 98304

// ============================================================================
// Scratch (device globals — no allocation allowed)
// ============================================================================
__device__ __align__(16) __half g_xh[(size_t)T_TOKENS * IN_F];  // 32 MB fp16 x
__device__ __align__(16) __half g_wh[(size_t)OUT_F * IN_F];     // 32 MB fp16 dense W

// ============================================================================
// Helpers
// ============================================================================
__device__ __forceinline__ uint32_t smem_u32(const void* p) {
    uint32_t a;
    asm("{ .reg .u64 t; cvta.to.shared.u64 t, %1; cvt.u32.u64 %0, t; }"
        : "=r"(a) : "l"(p));
    return a;
}
#define SW128(o) ((o) ^ (((o) >> 3) & 0x70))

__device__ __forceinline__ void cp_async16(uint32_t dst, const void* src) {
    asm volatile("cp.async.cg.shared.global [%0], [%1], 16;" :: "r"(dst), "l"(src));
}
__device__ __forceinline__ void cp_commit() {
    asm volatile("cp.async.commit_group;" ::: "memory");
}
__device__ __forceinline__ void ldmatrix_x4(uint32_t* r, uint32_t addr) {
    asm volatile("ldmatrix.sync.aligned.m8n8.x4.shared.b16 {%0,%1,%2,%3}, [%4];"
                 : "=r"(r[0]), "=r"(r[1]), "=r"(r[2]), "=r"(r[3]) : "r"(addr));
}
__device__ __forceinline__ void mma16816(float* c, const uint32_t* a,
                                         uint32_t b0, uint32_t b1) {
    asm volatile(
        "mma.sync.aligned.m16n8k16.row.col.f32.f16.f16.f32 "
        "{%0,%1,%2,%3}, {%4,%5,%6,%7}, {%8,%9}, {%0,%1,%2,%3};"
        : "+f"(c[0]), "+f"(c[1]), "+f"(c[2]), "+f"(c[3])
        : "r"(a[0]), "r"(a[1]), "r"(a[2]), "r"(a[3]), "r"(b0), "r"(b1));
}

// ============================================================================
// Kernel 1: fp32 x -> fp16 (vectorized)
// ============================================================================
__global__ void k_convert_x(const float4* __restrict__ x) {
    size_t i = (size_t)blockIdx.x * blockDim.x + threadIdx.x;
    float4 v = x[i];
    __half2* xh2 = reinterpret_cast<__half2*>(g_xh);
    xh2[2 * i]     = __floats2half2_rn(v.x, v.y);
    xh2[2 * i + 1] = __floats2half2_rn(v.z, v.w);
}

// ============================================================================
// Kernel 2: scatter condensed rows to dense fp16 W. Indices are sorted per
// row, so duplicate runs are summed in fp32 by the run-leader thread —
// deterministic, no atomics.
// ============================================================================
__global__ void k_densify(const float* __restrict__ w, const int* __restrict__ mask) {
    __shared__ float acc[IN_F];
    const int o = blockIdx.x;
    const int tid = threadIdx.x;
    for (int j = tid; j < IN_F; j += blockDim.x) acc[j] = 0.0f;
    __syncthreads();

    const int* mrow = mask + (size_t)o * NNZ;
    const float* wrow = w + (size_t)o * NNZ;
    for (int j = tid; j < NNZ; j += blockDim.x) {
        int m = mrow[j];
        if (j > 0 && mrow[j - 1] == m) continue;  // not the run leader
        float s = wrow[j];
        int jj = j + 1;
        while (jj < NNZ && mrow[jj] == m) { s += wrow[jj]; jj++; }
        acc[m] = s;  // unique owner, acc pre-zeroed
    }
    __syncthreads();

    __half* dst = g_wh + (size_t)o * IN_F;
    for (int j = tid; j < IN_F; j += blockDim.x)
        dst[j] = __float2half_rn(acc[j]);
}

// ============================================================================
// Kernel 3: pipelined fp16 mma.sync GEMM
//   out[T,O] = xh[T,In] * Wh[O,In]^T + bias
// CTA 128x128, BK=64, 3-stage cp.async pipeline, 8 warps @ 64x32 warp tiles.
// Both A and B are K-major in smem (128B rows, SW128 swizzle) -> non-trans
// ldmatrix for both operands.
// ============================================================================
__global__ void __launch_bounds__(256, 1) k_gemm(const float* __restrict__ bias,
                                                 float* __restrict__ out) {
    extern __shared__ char smem[];
    const uint32_t sbase = smem_u32(smem);
    const int tid  = threadIdx.x;
    const int wid  = tid >> 5;
    const int lane = tid & 31;
    const int wm = (wid >> 2) * 64;   // warp row offset within CTA tile
    const int wn = (wid & 3) * 32;    // warp col offset
    const int tok0 = blockIdx.x * BM;
    const int o0   = blockIdx.y * BN;

    const __half* ga = g_xh + (size_t)tok0 * IN_F;
    const __half* gb = g_wh + (size_t)o0 * IN_F;

    // per-thread gmem->smem mapping: 4 (row, 16B-chunk) pairs per operand
    const int ldrow = tid >> 3;        // 0..31 step base, +32 per i
    const int ldc   = (tid & 7) * 16;  // byte offset within 128B row

    auto load_stage = [&](int it, int s) {
        const uint32_t sA = sbase + s * STAGE_BYTES;
        const uint32_t sB = sA + BM * BK * 2;
        const size_t gk = (size_t)it * BK + (ldc >> 1);  // halves
        #pragma unroll
        for (int i = 0; i < 4; ++i) {
            const int row = ldrow + i * 32;
            const uint32_t off = SW128(row * 128 + ldc);
            cp_async16(sA + off, ga + (size_t)row * IN_F + gk);
            cp_async16(sB + off, gb + (size_t)row * IN_F + gk);
        }
    };

    load_stage(0, 0); cp_commit();
    load_stage(1, 1); cp_commit();

    float acc[4][4][4];
    #pragma unroll
    for (int i = 0; i < 4; ++i)
        #pragma unroll
        for (int j = 0; j < 4; ++j)
            #pragma unroll
            for (int k = 0; k < 4; ++k) acc[i][j][k] = 0.0f;

    // ldmatrix lane-address components (constant across iterations)
    const int a_m  = wm + (lane & 15);          // A: quad pairs 0-1 rows, 2-3 +k8
    const int a_kb = (lane >> 4) * 16;          // byte
    const int b_n  = wn + (lane & 7) + ((lane >> 4) << 3);  // quads 0,1:n0-7 2,3:n8-15
    const int b_kb = ((lane >> 3) & 1) * 16;

    for (int j = 0; j < KITERS; ++j) {
        asm volatile("cp.async.wait_group 1;" ::: "memory");
        __syncthreads();

        const uint32_t sA = sbase + (j % 3) * STAGE_BYTES;
        const uint32_t sB = sA + BM * BK * 2;

        #pragma unroll
        for (int ks = 0; ks < BK / 16; ++ks) {
            const int kb = ks * 32;  // bytes
            uint32_t af[4][4];
            #pragma unroll
            for (int tm = 0; tm < 4; ++tm)
                ldmatrix_x4(af[tm], sA + SW128((a_m + tm * 16) * 128 + kb + a_kb));
            uint32_t bf[2][4];
            #pragma unroll
            for (int tn2 = 0; tn2 < 2; ++tn2)
                ldmatrix_x4(bf[tn2], sB + SW128((b_n + tn2 * 16) * 128 + kb + b_kb));
            #pragma unroll
            for (int tm = 0; tm < 4; ++tm)
                #pragma unroll
                for (int tn = 0; tn < 4; ++tn)
                    mma16816(acc[tm][tn], af[tm], bf[tn >> 1][(tn & 1) * 2],
                             bf[tn >> 1][(tn & 1) * 2 + 1]);
        }

        if (j + 2 < KITERS) load_stage(j + 2, (j + 2) % 3);
        cp_commit();
    }

    // ---- Epilogue: direct register -> gmem (float2), + bias
    #pragma unroll
    for (int tm = 0; tm < 4; ++tm) {
        const int row = tok0 + wm + tm * 16 + (lane >> 2);
        #pragma unroll
        for (int tn = 0; tn < 4; ++tn) {
            const int col = o0 + wn + tn * 8 + 2 * (lane & 3);
            const float2 bv = *reinterpret_cast<const float2*>(bias + col);
            float2 v0 = {acc[tm][tn][0] + bv.x, acc[tm][tn][1] + bv.y};
            float2 v1 = {acc[tm][tn][2] + bv.x, acc[tm][tn][3] + bv.y};
            *reinterpret_cast<float2*>(out + (size_t)row * OUT_F + col) = v0;
            *reinterpret_cast<float2*>(out + (size_t)(row + 8) * OUT_F + col) = v1;
        }
    }
}

// ============================================================================
// Launch
// ============================================================================
extern "C" void kernel_launch(void* const* d_in, const int* in_sizes, int n_in,
                              void* d_out, int out_size) {
    const float* x    = (const float*)d_in[0];
    const float* w    = (const float*)d_in[1];
    const int*   mask = (const int*)d_in[2];
    const float* bias = (const float*)d_in[3];
    float* out = (float*)d_out;

    cudaFuncSetAttribute(k_gemm, cudaFuncAttributeMaxDynamicSharedMemorySize,
                         SMEM_TOTAL);

    k_convert_x<<<(T_TOKENS * IN_F / 4) / 256, 256>>>((const float4*)x);
    k_densify<<<OUT_F, 128>>>(w, mask);
    k_gemm<<<dim3(T_TOKENS / BM, OUT_F / BN), 256, SMEM_TOTAL>>>(bias, out);
}

// round 3
// speedup vs baseline: 1.0063x; 1.0063x over previous
#include <cuda_runtime.h>
#include <cuda_fp16.h>
#include <cstdint>

// ============================================================================
// Problem constants
// ============================================================================
#define T_TOKENS 4096
#define IN_F     4096
#define OUT_F    4096
#define NNZ      512

// GEMM tiling: CTA 256x128, warp tile 64x64 (8 warps, 4x2 grid)
static constexpr int BM = 256;
static constexpr int BN = 128;
static constexpr int BK = 64;                 // fp16 -> 128B rows (SW128 atom)
static constexpr int KITERS = IN_F / BK;      // 64
static constexpr int STAGES = 3;
static constexpr int STAGE_BYTES = (BM * BK + BN * BK) * 2;  // 49152
static constexpr int SMEM_TOTAL = STAGES * STAGE_BYTES;      // 147456

// fused prep kernel split
static constexpr int CONV_BLOCKS = (T_TOKENS * IN_F / 4) / 256;  // 16384

// ============================================================================
// Scratch (device globals — no allocation allowed)
// ============================================================================
__device__ __align__(16) __half g_xh[(size_t)T_TOKENS * IN_F];  // 32 MB fp16 x
__device__ __align__(16) __half g_wh[(size_t)OUT_F * IN_F];     // 32 MB fp16 dense W

// ============================================================================
// Helpers
// ============================================================================
__device__ __forceinline__ uint32_t smem_u32(const void* p) {
    uint32_t a;
    asm("{ .reg .u64 t; cvta.to.shared.u64 t, %1; cvt.u32.u64 %0, t; }"
        : "=r"(a) : "l"(p));
    return a;
}
#define SW128(o) ((o) ^ (((o) >> 3) & 0x70))

__device__ __forceinline__ void cp_async16(uint32_t dst, const void* src) {
    asm volatile("cp.async.cg.shared.global [%0], [%1], 16;" :: "r"(dst), "l"(src));
}
__device__ __forceinline__ void cp_commit() {
    asm volatile("cp.async.commit_group;" ::: "memory");
}
__device__ __forceinline__ void ldmatrix_x4(uint32_t* r, uint32_t addr) {
    asm volatile("ldmatrix.sync.aligned.m8n8.x4.shared.b16 {%0,%1,%2,%3}, [%4];"
                 : "=r"(r[0]), "=r"(r[1]), "=r"(r[2]), "=r"(r[3]) : "r"(addr));
}
__device__ __forceinline__ void mma16816(float* c, const uint32_t* a,
                                         uint32_t b0, uint32_t b1) {
    asm volatile(
        "mma.sync.aligned.m16n8k16.row.col.f32.f16.f16.f32 "
        "{%0,%1,%2,%3}, {%4,%5,%6,%7}, {%8,%9}, {%0,%1,%2,%3};"
        : "+f"(c[0]), "+f"(c[1]), "+f"(c[2]), "+f"(c[3])
        : "r"(a[0]), "r"(a[1]), "r"(a[2]), "r"(a[3]), "r"(b0), "r"(b1));
}

// ============================================================================
// Kernel 1 (fused prep): blocks [0, CONV_BLOCKS) convert x fp32->fp16;
// blocks [CONV_BLOCKS, +OUT_F) densify one W row each. The two phases touch
// disjoint data and overlap across SMs instead of serializing as two kernels.
// ============================================================================
__global__ void __launch_bounds__(256) k_prep(const float4* __restrict__ x,
                                              const float* __restrict__ w,
                                              const int* __restrict__ mask) {
    if (blockIdx.x < CONV_BLOCKS) {
        size_t i = (size_t)blockIdx.x * 256 + threadIdx.x;
        float4 v = x[i];
        __half2* xh2 = reinterpret_cast<__half2*>(g_xh);
        xh2[2 * i]     = __floats2half2_rn(v.x, v.y);
        xh2[2 * i + 1] = __floats2half2_rn(v.z, v.w);
        return;
    }
    // ---- densify: indices sorted per row; duplicate runs summed in fp32 by
    // the run-leader thread — deterministic, no atomics.
    __shared__ float acc[IN_F];
    const int o = blockIdx.x - CONV_BLOCKS;
    const int tid = threadIdx.x;
    for (int j = tid; j < IN_F; j += 256) acc[j] = 0.0f;
    __syncthreads();

    const int* mrow = mask + (size_t)o * NNZ;
    const float* wrow = w + (size_t)o * NNZ;
    for (int j = tid; j < NNZ; j += 256) {
        int m = mrow[j];
        if (j > 0 && mrow[j - 1] == m) continue;  // not the run leader
        float s = wrow[j];
        int jj = j + 1;
        while (jj < NNZ && mrow[jj] == m) { s += wrow[jj]; jj++; }
        acc[m] = s;  // unique owner, acc pre-zeroed
    }
    __syncthreads();

    __half2* dst = reinterpret_cast<__half2*>(g_wh + (size_t)o * IN_F);
    for (int j = tid; j < IN_F / 2; j += 256)
        dst[j] = __floats2half2_rn(acc[2 * j], acc[2 * j + 1]);
}

// ============================================================================
// Kernel 2: pipelined fp16 mma.sync GEMM
//   out[T,O] = xh[T,In] * Wh[O,In]^T + bias
// CTA 256x128, BK=64, 3-stage cp.async pipeline, 8 warps @ 64x64 warp tiles.
// Both operands K-major in smem (128B rows, SW128) -> non-trans ldmatrix.
// B fragments consumed immediately after each ldmatrix (one bf[4] live).
// ============================================================================
__global__ void __launch_bounds__(256, 1) k_gemm(const float* __restrict__ bias,
                                                 float* __restrict__ out) {
    extern __shared__ char smem[];
    const uint32_t sbase = smem_u32(smem);
    const int tid  = threadIdx.x;
    const int wid  = tid >> 5;
    const int lane = tid & 31;
    const int wm = (wid >> 1) * 64;   // warp row offset (0..192)
    const int wn = (wid & 1) * 64;    // warp col offset (0/64)
    const int tok0 = blockIdx.x * BM;
    const int o0   = blockIdx.y * BN;

    const __half* ga = g_xh + (size_t)tok0 * IN_F;
    const __half* gb = g_wh + (size_t)o0 * IN_F;

    // gmem->smem mapping: A = 2048 16B chunks (8/thread), B = 1024 (4/thread)
    const int ldrow = tid >> 3;        // 0..31
    const int ldc   = (tid & 7) * 16;  // byte offset within 128B row
    const size_t gkc = (size_t)(ldc >> 1);

    auto load_stage = [&](int it, int s) {
        const uint32_t sA = sbase + s * STAGE_BYTES;
        const uint32_t sB = sA + BM * BK * 2;
        const size_t gk = (size_t)it * BK + gkc;
        #pragma unroll
        for (int i = 0; i < 8; ++i) {
            const int row = ldrow + i * 32;
            cp_async16(sA + SW128(row * 128 + ldc), ga + (size_t)row * IN_F + gk);
        }
        #pragma unroll
        for (int i = 0; i < 4; ++i) {
            const int row = ldrow + i * 32;
            cp_async16(sB + SW128(row * 128 + ldc), gb + (size_t)row * IN_F + gk);
        }
    };

    load_stage(0, 0); cp_commit();
    load_stage(1, 1); cp_commit();

    float acc[4][8][4];
    #pragma unroll
    for (int i = 0; i < 4; ++i)
        #pragma unroll
        for (int j = 0; j < 8; ++j)
            #pragma unroll
            for (int k = 0; k < 4; ++k) acc[i][j][k] = 0.0f;

    // ldmatrix lane-address components (constant across iterations)
    const int a_m  = wm + (lane & 15);
    const int a_kb = (lane >> 4) * 16;
    const int b_n  = wn + (lane & 7) + ((lane >> 4) << 3);
    const int b_kb = ((lane >> 3) & 1) * 16;

    for (int j = 0; j < KITERS; ++j) {
        asm volatile("cp.async.wait_group 1;" ::: "memory");
        __syncthreads();

        const uint32_t sA = sbase + (j % 3) * STAGE_BYTES;
        const uint32_t sB = sA + BM * BK * 2;

        #pragma unroll
        for (int ks = 0; ks < BK / 16; ++ks) {
            const int kb = ks * 32;  // bytes
            uint32_t af[4][4];
            #pragma unroll
            for (int tm = 0; tm < 4; ++tm)
                ldmatrix_x4(af[tm], sA + SW128((a_m + tm * 16) * 128 + kb + a_kb));
            #pragma unroll
            for (int tn2 = 0; tn2 < 4; ++tn2) {
                uint32_t bf[4];
                ldmatrix_x4(bf, sB + SW128((b_n + tn2 * 16) * 128 + kb + b_kb));
                #pragma unroll
                for (int tm = 0; tm < 4; ++tm) {
                    mma16816(acc[tm][2 * tn2],     af[tm], bf[0], bf[1]);
                    mma16816(acc[tm][2 * tn2 + 1], af[tm], bf[2], bf[3]);
                }
            }
        }

        if (j + 2 < KITERS) load_stage(j + 2, (j + 2) % 3);
        cp_commit();
    }

    // ---- Epilogue: direct register -> gmem (float2), + bias
    #pragma unroll
    for (int tm = 0; tm < 4; ++tm) {
        const int row = tok0 + wm + tm * 16 + (lane >> 2);
        #pragma unroll
        for (int tn = 0; tn < 8; ++tn) {
            const int col = o0 + wn + tn * 8 + 2 * (lane & 3);
            const float2 bv = *reinterpret_cast<const float2*>(bias + col);
            float2 v0 = {acc[tm][tn][0] + bv.x, acc[tm][tn][1] + bv.y};
            float2 v1 = {acc[tm][tn][2] + bv.x, acc[tm][tn][3] + bv.y};
            *reinterpret_cast<float2*>(out + (size_t)row * OUT_F + col) = v0;
            *reinterpret_cast<float2*>(out + (size_t)(row + 8) * OUT_F + col) = v1;
        }
    }
}

// ============================================================================
// Launch
// ============================================================================
extern "C" void kernel_launch(void* const* d_in, const int* in_sizes, int n_in,
                              void* d_out, int out_size) {
    const float* x    = (const float*)d_in[0];
    const float* w    = (const float*)d_in[1];
    const int*   mask = (const int*)d_in[2];
    const float* bias = (const float*)d_in[3];
    float* out = (float*)d_out;

    cudaFuncSetAttribute(k_gemm, cudaFuncAttributeMaxDynamicSharedMemorySize,
                         SMEM_TOTAL);

    k_prep<<<CONV_BLOCKS + OUT_F, 256>>>((const float4*)x, w, mask);
    k_gemm<<<dim3(T_TOKENS / BM, OUT_F / BN), 256, SMEM_TOTAL>>>(bias, out);
}

// round 4
// speedup vs baseline: 1.1161x; 1.1091x over previous
#include <cuda_runtime.h>
#include <cuda_fp16.h>
#include <cstdint>

// ============================================================================
// Problem constants
// ============================================================================
#define T_TOKENS 4096
#define IN_F     4096
#define OUT_F    4096
#define NNZ      512

// GEMM tiling: CTA 128x128, warp tile 64x32 (8 warps, 2x4), 2 CTAs/SM
static constexpr int BM = 128;
static constexpr int BN = 128;
static constexpr int BK = 64;                 // fp16 -> 128B rows (SW128 atom)
static constexpr int KITERS = IN_F / BK;      // 64
static constexpr int STAGES = 3;
static constexpr int STAGE_BYTES = (BM * BK + BN * BK) * 2;  // 32768
static constexpr int SMEM_TOTAL = STAGES * STAGE_BYTES;      // 98304 (96KB)

// fused prep kernel split
static constexpr int CONV_BLOCKS = (T_TOKENS * IN_F / 4) / 256;  // 16384

// ============================================================================
// Scratch (device globals — no allocation allowed)
// ============================================================================
__device__ __align__(16) __half g_xh[(size_t)T_TOKENS * IN_F];  // 32 MB fp16 x
__device__ __align__(16) __half g_wh[(size_t)OUT_F * IN_F];     // 32 MB fp16 dense W

// ============================================================================
// Helpers
// ============================================================================
__device__ __forceinline__ uint32_t smem_u32(const void* p) {
    uint32_t a;
    asm("{ .reg .u64 t; cvta.to.shared.u64 t, %1; cvt.u32.u64 %0, t; }"
        : "=r"(a) : "l"(p));
    return a;
}
#define SW128(o) ((o) ^ (((o) >> 3) & 0x70))

__device__ __forceinline__ void cp_async16(uint32_t dst, const void* src) {
    asm volatile("cp.async.cg.shared.global [%0], [%1], 16;" :: "r"(dst), "l"(src));
}
__device__ __forceinline__ void cp_commit() {
    asm volatile("cp.async.commit_group;" ::: "memory");
}
__device__ __forceinline__ void ldmatrix_x4(uint32_t* r, uint32_t addr) {
    asm volatile("ldmatrix.sync.aligned.m8n8.x4.shared.b16 {%0,%1,%2,%3}, [%4];"
                 : "=r"(r[0]), "=r"(r[1]), "=r"(r[2]), "=r"(r[3]) : "r"(addr));
}
__device__ __forceinline__ void mma16816(float* c, const uint32_t* a,
                                         uint32_t b0, uint32_t b1) {
    asm volatile(
        "mma.sync.aligned.m16n8k16.row.col.f32.f16.f16.f32 "
        "{%0,%1,%2,%3}, {%4,%5,%6,%7}, {%8,%9}, {%0,%1,%2,%3};"
        : "+f"(c[0]), "+f"(c[1]), "+f"(c[2]), "+f"(c[3])
        : "r"(a[0]), "r"(a[1]), "r"(a[2]), "r"(a[3]), "r"(b0), "r"(b1));
}

// ============================================================================
// Kernel 1 (fused prep): blocks [0, CONV_BLOCKS) convert x fp32->fp16;
// blocks [CONV_BLOCKS, +OUT_F) densify one W row each.
// ============================================================================
__global__ void __launch_bounds__(256) k_prep(const float4* __restrict__ x,
                                              const float* __restrict__ w,
                                              const int* __restrict__ mask) {
    if (blockIdx.x < CONV_BLOCKS) {
        size_t i = (size_t)blockIdx.x * 256 + threadIdx.x;
        float4 v = x[i];
        __half2* xh2 = reinterpret_cast<__half2*>(g_xh);
        xh2[2 * i]     = __floats2half2_rn(v.x, v.y);
        xh2[2 * i + 1] = __floats2half2_rn(v.z, v.w);
        return;
    }
    // ---- densify: indices sorted per row; duplicate runs summed in fp32 by
    // the run-leader thread — deterministic, no atomics.
    __shared__ float acc[IN_F];
    const int o = blockIdx.x - CONV_BLOCKS;
    const int tid = threadIdx.x;
    for (int j = tid; j < IN_F; j += 256) acc[j] = 0.0f;
    __syncthreads();

    const int* mrow = mask + (size_t)o * NNZ;
    const float* wrow = w + (size_t)o * NNZ;
    for (int j = tid; j < NNZ; j += 256) {
        int m = mrow[j];
        if (j > 0 && mrow[j - 1] == m) continue;  // not the run leader
        float s = wrow[j];
        int jj = j + 1;
        while (jj < NNZ && mrow[jj] == m) { s += wrow[jj]; jj++; }
        acc[m] = s;  // unique owner, acc pre-zeroed
    }
    __syncthreads();

    __half2* dst = reinterpret_cast<__half2*>(g_wh + (size_t)o * IN_F);
    for (int j = tid; j < IN_F / 2; j += 256)
        dst[j] = __floats2half2_rn(acc[2 * j], acc[2 * j + 1]);
}

// ============================================================================
// Kernel 2: pipelined fp16 mma.sync GEMM, 2 CTAs/SM for bubble coverage.
//   out[T,O] = xh[T,In] * Wh[O,In]^T + bias
// CTA 128x128, BK=64, 3-stage cp.async pipeline, 8 warps @ 64x32.
// Next-stage loads issued immediately after the barrier (stage freed by it),
// giving cp.async a full iteration of latency cover before its wait.
// ============================================================================
__global__ void __launch_bounds__(256, 2) k_gemm(const float* __restrict__ bias,
                                                 float* __restrict__ out) {
    extern __shared__ char smem[];
    const uint32_t sbase = smem_u32(smem);
    const int tid  = threadIdx.x;
    const int wid  = tid >> 5;
    const int lane = tid & 31;
    const int wm = (wid >> 2) * 64;   // warp row offset
    const int wn = (wid & 3) * 32;    // warp col offset
    const int tok0 = blockIdx.x * BM;
    const int o0   = blockIdx.y * BN;

    const __half* ga = g_xh + (size_t)tok0 * IN_F;
    const __half* gb = g_wh + (size_t)o0 * IN_F;

    // gmem->smem mapping: 4 (row, 16B-chunk) pairs per operand per thread
    const int ldrow = tid >> 3;        // 0..31
    const int ldc   = (tid & 7) * 16;  // byte offset within 128B row
    const size_t gkc = (size_t)(ldc >> 1);

    auto load_stage = [&](int it, int s) {
        const uint32_t sA = sbase + s * STAGE_BYTES;
        const uint32_t sB = sA + BM * BK * 2;
        const size_t gk = (size_t)it * BK + gkc;
        #pragma unroll
        for (int i = 0; i < 4; ++i) {
            const int row = ldrow + i * 32;
            const uint32_t off = SW128(row * 128 + ldc);
            cp_async16(sA + off, ga + (size_t)row * IN_F + gk);
            cp_async16(sB + off, gb + (size_t)row * IN_F + gk);
        }
        cp_commit();
    };

    load_stage(0, 0);
    load_stage(1, 1);

    float acc[4][4][4];
    #pragma unroll
    for (int i = 0; i < 4; ++i)
        #pragma unroll
        for (int j = 0; j < 4; ++j)
            #pragma unroll
            for (int k = 0; k < 4; ++k) acc[i][j][k] = 0.0f;

    // ldmatrix lane-address components (constant across iterations)
    const int a_m  = wm + (lane & 15);
    const int a_kb = (lane >> 4) * 16;
    const int b_n  = wn + (lane & 7) + ((lane >> 4) << 3);
    const int b_kb = ((lane >> 3) & 1) * 16;

    for (int j = 0; j < KITERS; ++j) {
        asm volatile("cp.async.wait_group 1;" ::: "memory");
        __syncthreads();

        // stage (j+2)%3 was freed by the barrier above -> prefetch now
        if (j + 2 < KITERS) load_stage(j + 2, (j + 2) % 3);

        const uint32_t sA = sbase + (j % 3) * STAGE_BYTES;
        const uint32_t sB = sA + BM * BK * 2;

        #pragma unroll
        for (int ks = 0; ks < BK / 16; ++ks) {
            const int kb = ks * 32;  // bytes
            uint32_t af[4][4];
            #pragma unroll
            for (int tm = 0; tm < 4; ++tm)
                ldmatrix_x4(af[tm], sA + SW128((a_m + tm * 16) * 128 + kb + a_kb));
            uint32_t bf[2][4];
            #pragma unroll
            for (int tn2 = 0; tn2 < 2; ++tn2)
                ldmatrix_x4(bf[tn2], sB + SW128((b_n + tn2 * 16) * 128 + kb + b_kb));
            #pragma unroll
            for (int tm = 0; tm < 4; ++tm)
                #pragma unroll
                for (int tn = 0; tn < 4; ++tn)
                    mma16816(acc[tm][tn], af[tm], bf[tn >> 1][(tn & 1) * 2],
                             bf[tn >> 1][(tn & 1) * 2 + 1]);
        }
    }

    // ---- Epilogue: direct register -> gmem (float2), + bias
    #pragma unroll
    for (int tm = 0; tm < 4; ++tm) {
        const int row = tok0 + wm + tm * 16 + (lane >> 2);
        #pragma unroll
        for (int tn = 0; tn < 4; ++tn) {
            const int col = o0 + wn + tn * 8 + 2 * (lane & 3);
            const float2 bv = *reinterpret_cast<const float2*>(bias + col);
            float2 v0 = {acc[tm][tn][0] + bv.x, acc[tm][tn][1] + bv.y};
            float2 v1 = {acc[tm][tn][2] + bv.x, acc[tm][tn][3] + bv.y};
            *reinterpret_cast<float2*>(out + (size_t)row * OUT_F + col) = v0;
            *reinterpret_cast<float2*>(out + (size_t)(row + 8) * OUT_F + col) = v1;
        }
    }
}

// ============================================================================
// Launch
// ============================================================================
extern "C" void kernel_launch(void* const* d_in, const int* in_sizes, int n_in,
                              void* d_out, int out_size) {
    const float* x    = (const float*)d_in[0];
    const float* w    = (const float*)d_in[1];
    const int*   mask = (const int*)d_in[2];
    const float* bias = (const float*)d_in[3];
    float* out = (float*)d_out;

    cudaFuncSetAttribute(k_gemm, cudaFuncAttributeMaxDynamicSharedMemorySize,
                         SMEM_TOTAL);

    k_prep<<<CONV_BLOCKS + OUT_F, 256>>>((const float4*)x, w, mask);
    k_gemm<<<dim3(T_TOKENS / BM, OUT_F / BN), 256, SMEM_TOTAL>>>(bias, out);
}

// round 5
// speedup vs baseline: 1.2245x; 1.0972x over previous
#include <cuda_runtime.h>
#include <cuda_fp16.h>
#include <cstdint>

// ============================================================================
// Problem constants
// ============================================================================
#define T_TOKENS 4096
#define IN_F     4096
#define OUT_F    4096
#define NNZ      512

// GEMM tiling: CTA 128x128, warp tile 64x32 (8 warps, 2x4), 2 CTAs/SM
static constexpr int BM = 128;
static constexpr int BN = 128;
static constexpr int BK = 64;                 // fp16 -> 128B rows (SW128 atom)
static constexpr int KITERS = IN_F / BK;      // 64
static constexpr int STAGES = 3;
static constexpr int STAGE_BYTES = (BM * BK + BN * BK) * 2;  // 32768
static constexpr int MBAR_BASE  = STAGES * STAGE_BYTES;      // 98304
// full[s] at MBAR_BASE + s*8, empty[s] at MBAR_BASE + 24 + s*8
static constexpr int SMEM_TOTAL = MBAR_BASE + 64;            // 98368

// fused prep kernel split
static constexpr int CONV_BLOCKS = (T_TOKENS * IN_F / 4) / 256;  // 16384

// ============================================================================
// Scratch (device globals — no allocation allowed)
// ============================================================================
__device__ __align__(16) __half g_xh[(size_t)T_TOKENS * IN_F];  // 32 MB fp16 x
__device__ __align__(16) __half g_wh[(size_t)OUT_F * IN_F];     // 32 MB fp16 dense W

// ============================================================================
// Helpers
// ============================================================================
__device__ __forceinline__ uint32_t smem_u32(const void* p) {
    uint32_t a;
    asm("{ .reg .u64 t; cvta.to.shared.u64 t, %1; cvt.u32.u64 %0, t; }"
        : "=r"(a) : "l"(p));
    return a;
}
#define SW128(o) ((o) ^ (((o) >> 3) & 0x70))

__device__ __forceinline__ void cp_async16(uint32_t dst, const void* src) {
    asm volatile("cp.async.cg.shared.global [%0], [%1], 16;" :: "r"(dst), "l"(src));
}
// arrive on mbar when ALL prior cp.asyncs of this thread have completed
__device__ __forceinline__ void cp_async_mbar_arrive(uint32_t mbar) {
    asm volatile("cp.async.mbarrier.arrive.noinc.shared.b64 [%0];"
                 :: "r"(mbar) : "memory");
}
__device__ __forceinline__ void mbar_init(uint32_t mbar, uint32_t cnt) {
    asm volatile("mbarrier.init.shared.b64 [%0], %1;" :: "r"(mbar), "r"(cnt)
                 : "memory");
}
__device__ __forceinline__ void mbar_arrive(uint32_t mbar) {
    asm volatile("mbarrier.arrive.release.cta.shared::cta.b64 _, [%0];"
                 :: "r"(mbar) : "memory");
}
__device__ __forceinline__ void mbar_wait(uint32_t mbar, uint32_t parity) {
    uint32_t done;
    asm volatile("{ .reg .pred p;\n\t"
        "mbarrier.try_wait.parity.acquire.cta.shared::cta.b64 p, [%1], %2;\n\t"
        "selp.b32 %0, 1, 0, p; }"
        : "=r"(done) : "r"(mbar), "r"(parity) : "memory");
    if (!done) {
        asm volatile("{ .reg .pred P1;\n\t"
            "WAIT_LOOP_%=:\n\t"
            "mbarrier.try_wait.parity.acquire.cta.shared::cta.b64 P1, [%0], %1, 0x989680;\n\t"
            "@P1 bra.uni WAIT_DONE_%=;\n\t"
            "bra.uni WAIT_LOOP_%=;\n\t"
            "WAIT_DONE_%=: }"
            :: "r"(mbar), "r"(parity) : "memory");
    }
}
__device__ __forceinline__ void ldmatrix_x4(uint32_t* r, uint32_t addr) {
    asm volatile("ldmatrix.sync.aligned.m8n8.x4.shared.b16 {%0,%1,%2,%3}, [%4];"
                 : "=r"(r[0]), "=r"(r[1]), "=r"(r[2]), "=r"(r[3]) : "r"(addr));
}
__device__ __forceinline__ void mma16816(float* c, const uint32_t* a,
                                         uint32_t b0, uint32_t b1) {
    asm volatile(
        "mma.sync.aligned.m16n8k16.row.col.f32.f16.f16.f32 "
        "{%0,%1,%2,%3}, {%4,%5,%6,%7}, {%8,%9}, {%0,%1,%2,%3};"
        : "+f"(c[0]), "+f"(c[1]), "+f"(c[2]), "+f"(c[3])
        : "r"(a[0]), "r"(a[1]), "r"(a[2]), "r"(a[3]), "r"(b0), "r"(b1));
}

// ============================================================================
// Kernel 1 (fused prep): blocks [0, CONV_BLOCKS) convert x fp32->fp16;
// blocks [CONV_BLOCKS, +OUT_F) densify one W row each.
// ============================================================================
__global__ void __launch_bounds__(256) k_prep(const float4* __restrict__ x,
                                              const float* __restrict__ w,
                                              const int* __restrict__ mask) {
    if (blockIdx.x < CONV_BLOCKS) {
        size_t i = (size_t)blockIdx.x * 256 + threadIdx.x;
        float4 v = x[i];
        __half2* xh2 = reinterpret_cast<__half2*>(g_xh);
        xh2[2 * i]     = __floats2half2_rn(v.x, v.y);
        xh2[2 * i + 1] = __floats2half2_rn(v.z, v.w);
        return;
    }
    // ---- densify: indices sorted per row; duplicate runs summed in fp32 by
    // the run-leader thread — deterministic, no atomics.
    __shared__ float acc[IN_F];
    const int o = blockIdx.x - CONV_BLOCKS;
    const int tid = threadIdx.x;
    for (int j = tid; j < IN_F; j += 256) acc[j] = 0.0f;
    __syncthreads();

    const int* mrow = mask + (size_t)o * NNZ;
    const float* wrow = w + (size_t)o * NNZ;
    for (int j = tid; j < NNZ; j += 256) {
        int m = mrow[j];
        if (j > 0 && mrow[j - 1] == m) continue;  // not the run leader
        float s = wrow[j];
        int jj = j + 1;
        while (jj < NNZ && mrow[jj] == m) { s += wrow[jj]; jj++; }
        acc[m] = s;  // unique owner, acc pre-zeroed
    }
    __syncthreads();

    __half2* dst = reinterpret_cast<__half2*>(g_wh + (size_t)o * IN_F);
    for (int j = tid; j < IN_F / 2; j += 256)
        dst[j] = __floats2half2_rn(acc[2 * j], acc[2 * j + 1]);
}

// ============================================================================
// Kernel 2: pipelined fp16 mma.sync GEMM, mbarrier producer/consumer ring.
//   out[T,O] = xh[T,In] * Wh[O,In]^T + bias
// CTA 128x128, BK=64, 3-stage ring, 8 warps @ 64x32, 2 CTAs/SM.
// No __syncthreads in the main loop: full[s] tracks cp.async completion
// (cp.async.mbarrier.arrive.noinc), empty[s] tracks all-warps-done-reading.
// Warps drift up to ~1 iteration, desynchronizing LDSM bursts so the tensor
// pipe stays fed through the load windows.
// ============================================================================
__global__ void __launch_bounds__(256, 2) k_gemm(const float* __restrict__ bias,
                                                 float* __restrict__ out) {
    extern __shared__ char smem[];
    const uint32_t sbase = smem_u32(smem);
    const int tid  = threadIdx.x;
    const int wid  = tid >> 5;
    const int lane = tid & 31;
    const int wm = (wid >> 2) * 64;   // warp row offset
    const int wn = (wid & 3) * 32;    // warp col offset
    const int tok0 = blockIdx.x * BM;
    const int o0   = blockIdx.y * BN;

    const uint32_t mb_full0  = sbase + MBAR_BASE;
    const uint32_t mb_empty0 = sbase + MBAR_BASE + 24;

    if (tid == 0) {
        #pragma unroll
        for (int s = 0; s < STAGES; ++s) {
            mbar_init(mb_full0 + s * 8, 256);   // one cp.async-arrive per thread
            mbar_init(mb_empty0 + s * 8, 256);  // one read-done arrive per thread
        }
    }
    __syncthreads();  // barriers visible before any use

    const __half* ga = g_xh + (size_t)tok0 * IN_F;
    const __half* gb = g_wh + (size_t)o0 * IN_F;

    // gmem->smem mapping: 4 (row, 16B-chunk) pairs per operand per thread
    const int ldrow = tid >> 3;        // 0..31
    const int ldc   = (tid & 7) * 16;  // byte offset within 128B row
    const size_t gkc = (size_t)(ldc >> 1);

    auto load_stage = [&](int it, int s) {
        const uint32_t sA = sbase + s * STAGE_BYTES;
        const uint32_t sB = sA + BM * BK * 2;
        const size_t gk = (size_t)it * BK + gkc;
        #pragma unroll
        for (int i = 0; i < 4; ++i) {
            const int row = ldrow + i * 32;
            const uint32_t off = SW128(row * 128 + ldc);
            cp_async16(sA + off, ga + (size_t)row * IN_F + gk);
            cp_async16(sB + off, gb + (size_t)row * IN_F + gk);
        }
        cp_async_mbar_arrive(mb_full0 + s * 8);
    };

    // Prologue: fill all 3 stages (fresh barriers -> no empty wait needed)
    #pragma unroll
    for (int s = 0; s < STAGES; ++s) load_stage(s, s);

    float acc[4][4][4];
    #pragma unroll
    for (int i = 0; i < 4; ++i)
        #pragma unroll
        for (int j = 0; j < 4; ++j)
            #pragma unroll
            for (int k = 0; k < 4; ++k) acc[i][j][k] = 0.0f;

    // ldmatrix lane-address components (constant across iterations)
    const int a_m  = wm + (lane & 15);
    const int a_kb = (lane >> 4) * 16;
    const int b_n  = wn + (lane & 7) + ((lane >> 4) << 3);
    const int b_kb = ((lane >> 3) & 1) * 16;

    for (int j = 0; j < KITERS; ++j) {
        const int cs = j % 3;
        const uint32_t ph = (uint32_t)(j / 3) & 1;
        mbar_wait(mb_full0 + cs * 8, ph);

        const uint32_t sA = sbase + cs * STAGE_BYTES;
        const uint32_t sB = sA + BM * BK * 2;

        #pragma unroll
        for (int ks = 0; ks < BK / 16; ++ks) {
            const int kb = ks * 32;  // bytes
            uint32_t af[4][4];
            #pragma unroll
            for (int tm = 0; tm < 4; ++tm)
                ldmatrix_x4(af[tm], sA + SW128((a_m + tm * 16) * 128 + kb + a_kb));
            uint32_t bf[2][4];
            #pragma unroll
            for (int tn2 = 0; tn2 < 2; ++tn2)
                ldmatrix_x4(bf[tn2], sB + SW128((b_n + tn2 * 16) * 128 + kb + b_kb));
            if (ks == BK / 16 - 1)
                mbar_arrive(mb_empty0 + cs * 8);  // all my reads of stage cs done
            #pragma unroll
            for (int tm = 0; tm < 4; ++tm)
                #pragma unroll
                for (int tn = 0; tn < 4; ++tn)
                    mma16816(acc[tm][tn], af[tm], bf[tn >> 1][(tn & 1) * 2],
                             bf[tn >> 1][(tn & 1) * 2 + 1]);
        }

        if (j + 3 < KITERS) {
            mbar_wait(mb_empty0 + cs * 8, ph);  // all warps done reading stage cs
            load_stage(j + 3, cs);
        }
    }

    // ---- Epilogue: direct register -> gmem (float2), + bias
    #pragma unroll
    for (int tm = 0; tm < 4; ++tm) {
        const int row = tok0 + wm + tm * 16 + (lane >> 2);
        #pragma unroll
        for (int tn = 0; tn < 4; ++tn) {
            const int col = o0 + wn + tn * 8 + 2 * (lane & 3);
            const float2 bv = *reinterpret_cast<const float2*>(bias + col);
            float2 v0 = {acc[tm][tn][0] + bv.x, acc[tm][tn][1] + bv.y};
            float2 v1 = {acc[tm][tn][2] + bv.x, acc[tm][tn][3] + bv.y};
            *reinterpret_cast<float2*>(out + (size_t)row * OUT_F + col) = v0;
            *reinterpret_cast<float2*>(out + (size_t)(row + 8) * OUT_F + col) = v1;
        }
    }
}

// ============================================================================
// Launch
// ============================================================================
extern "C" void kernel_launch(void* const* d_in, const int* in_sizes, int n_in,
                              void* d_out, int out_size) {
    const float* x    = (const float*)d_in[0];
    const float* w    = (const float*)d_in[1];
    const int*   mask = (const int*)d_in[2];
    const float* bias = (const float*)d_in[3];
    float* out = (float*)d_out;

    cudaFuncSetAttribute(k_gemm, cudaFuncAttributeMaxDynamicSharedMemorySize,
                         SMEM_TOTAL);

    k_prep<<<CONV_BLOCKS + OUT_F, 256>>>((const float4*)x, w, mask);
    k_gemm<<<dim3(T_TOKENS / BM, OUT_F / BN), 256, SMEM_TOTAL>>>(bias, out);
}